// round 6
// baseline (speedup 1.0000x reference)
#include <cuda_runtime.h>
#include <cuda_fp16.h>

// GPTQ int4 dequant GEMM via HMMA: out[32,8192] = x @ dequant(W)^T + bias
// M=32, K=8192, N=8192, group=64. packed int32 element = one byte = 2 k-nibbles.
// v6: mma.sync.m16n8k16 core (v5) + 4-deep cp.async ring (1 barrier/group,
// >=2 groups always in flight) + red.global.v2.f32 epilogue (half the atomics).

#define MM 32
#define KDIM 8192
#define NDIM 8192
#define GS 64
#define NGROUPS 128
#define NTHREADS 256
#define NBLK 128           // n per CTA
#define KSPLIT 16
#define KPER 512           // k per CTA
#define GROUPS_PER 8       // KPER / GS
#define NRING 4            // cp.async ring depth (groups)
#define WROW 36            // int32 per ws row (32 data + 4 pad = 144B stride)
#define WBUF (NBLK * WROW) // int32 per ring buffer (one group)
#define WS_BYTES (NRING * WBUF * 4)
#define XROWH 520          // halfs per xs row (512 + 8 pad = 1040B stride)

__device__ __forceinline__ unsigned smem_u32(const void* p) {
    unsigned a;
    asm("{ .reg .u64 t; cvta.to.shared.u64 t, %1; cvt.u32.u64 %0, t; }"
        : "=r"(a) : "l"(p));
    return a;
}
__device__ __forceinline__ void cp_async16(unsigned saddr, const void* gptr) {
    asm volatile("cp.async.cg.shared.global [%0], [%1], 16;\n"
                 :: "r"(saddr), "l"(gptr));
}
__device__ __forceinline__ void cp_commit() {
    asm volatile("cp.async.commit_group;\n" ::: "memory");
}
template <int N>
__device__ __forceinline__ void cp_wait() {
    asm volatile("cp.async.wait_group %0;\n" :: "n"(N) : "memory");
}
__device__ __forceinline__ void ldsm4(unsigned& r0, unsigned& r1,
                                      unsigned& r2, unsigned& r3, unsigned a) {
    asm volatile("ldmatrix.sync.aligned.m8n8.x4.shared.b16 {%0,%1,%2,%3}, [%4];"
                 : "=r"(r0), "=r"(r1), "=r"(r2), "=r"(r3) : "r"(a));
}
__device__ __forceinline__ void mma16816(float d[4], const unsigned a[4],
                                         const unsigned b[2]) {
    asm volatile(
        "mma.sync.aligned.m16n8k16.row.col.f32.f16.f16.f32 "
        "{%0,%1,%2,%3}, {%4,%5,%6,%7}, {%8,%9}, {%0,%1,%2,%3};"
        : "+f"(d[0]), "+f"(d[1]), "+f"(d[2]), "+f"(d[3])
        : "r"(a[0]), "r"(a[1]), "r"(a[2]), "r"(a[3]), "r"(b[0]), "r"(b[1]));
}
__device__ __forceinline__ void red2(float* p, float a, float b) {
    asm volatile("red.global.add.v2.f32 [%0], {%1, %2};"
                 :: "l"(p), "f"(a), "f"(b) : "memory");
}
// dequant one packed byte (2 nibbles) -> fp16x2 {lo=even k, hi=odd k}
// f = 1 + q/16 exactly via mantissa OR; w = A*f + B = s*q - s*z (fp32), round once.
__device__ __forceinline__ unsigned dq2(int b, float Ag, float Bg) {
    unsigned flo = 0x3F800000u | (((unsigned)b << 19) & 0x00780000u);
    unsigned fhi = 0x3F800000u | (((unsigned)b << 15) & 0x00780000u);
    float wl = fmaf(Ag, __uint_as_float(flo), Bg);
    float wh = fmaf(Ag, __uint_as_float(fhi), Bg);
    unsigned r;
    asm("cvt.rn.f16x2.f32 %0, %2, %1;" : "=r"(r) : "f"(wl), "f"(wh)); // hi=wh, lo=wl
    return r;
}

__global__ void __launch_bounds__(NTHREADS)
gptq_init(const float* __restrict__ bias, float* __restrict__ out) {
    int i = blockIdx.x * NTHREADS + threadIdx.x;
    out[i] = bias[i & (NDIM - 1)];
}

extern __shared__ char smem_raw[];

__global__ void __launch_bounds__(NTHREADS, 2)
gptq_main(const float* __restrict__ x, const int* __restrict__ pw,
          const float* __restrict__ scales, const float* __restrict__ zeros,
          float* __restrict__ out)
{
    int* ws = reinterpret_cast<int*>(smem_raw);                      // [NRING][128][WROW]
    __half* xs = reinterpret_cast<__half*>(smem_raw + WS_BYTES);     // [32][XROWH]

    const int tid = threadIdx.x;
    const int w = tid >> 5;
    const int l = tid & 31;
    const int nblock0 = blockIdx.x * NBLK;
    const int k0 = blockIdx.y * KPER;
    const int g0 = blockIdx.y * GROUPS_PER;

    const unsigned ws_base = smem_u32(ws);
    const int s_chunk = tid & 7;        // 16B chunk within row's group slice
    const int s_row0  = tid >> 3;       // rows s_row0 + 32*i, i<4

    auto stage_w = [&](int g) {
        const int* gsrc = pw + ((k0 + g * GS) >> 1) + s_chunk * 4;
        unsigned sdst = ws_base +
            (unsigned)((g & (NRING - 1)) * WBUF + s_row0 * WROW + s_chunk * 4) * 4u;
#pragma unroll
        for (int i = 0; i < 4; ++i)
            cp_async16(sdst + (unsigned)(i * 32 * WROW) * 4u,
                       gsrc + (size_t)(nblock0 + s_row0 + i * 32) * (KDIM / 2));
        cp_commit();
    };
    stage_w(0);
    stage_w(1);
    stage_w(2);

    // ---- stage x: [32 m][KPER k] fp32 -> fp16 in smem (overlaps cp.async) ----
    {
        unsigned* xsu = reinterpret_cast<unsigned*>(xs);
#pragma unroll
        for (int i = 0; i < 16; ++i) {
            int lin = tid + i * NTHREADS;  // 0..4095 float4s
            int v = lin & 127;
            int m = lin >> 7;
            float4 xv = *reinterpret_cast<const float4*>(x + (size_t)m * KDIM + k0 + 4 * v);
            __half2 h0 = __floats2half2_rn(xv.x, xv.y);
            __half2 h1 = __floats2half2_rn(xv.z, xv.w);
            int idx = m * (XROWH / 2) + v * 2;
            xsu[idx]     = *reinterpret_cast<unsigned*>(&h0);
            xsu[idx + 1] = *reinterpret_cast<unsigned*>(&h1);
        }
    }

    // ---- dequant constants per (n-tile, group) ----
    float AA[2][GROUPS_PER], BB[2][GROUPS_PER];
#pragma unroll
    for (int t = 0; t < 2; ++t) {
        const int n = nblock0 + w * 16 + t * 8 + (l >> 2);
#pragma unroll
        for (int g = 0; g < GROUPS_PER; ++g) {
            float s = __ldg(scales + (size_t)n * NGROUPS + g0 + g);
            float z = __ldg(zeros  + (size_t)n * NGROUPS + g0 + g);
            AA[t][g] = 16.0f * s;
            BB[t][g] = -s * (z + 16.0f);
        }
    }

    // A-fragment ldmatrix lane addresses
    const unsigned xs_base = smem_u32(xs);
    const unsigned xa0 = xs_base + (unsigned)((l & 15) * XROWH * 2) + (unsigned)((l >> 4) * 16);
    const unsigned xa1 = xa0 + 16u * XROWH * 2;

    // weight smem indices: lane reads int32 (k-pair) (l&3) and (l&3)+4 of its row
    const int wr0 = (w * 16 + 0 + (l >> 2)) * WROW + (l & 3);
    const int wr1 = (w * 16 + 8 + (l >> 2)) * WROW + (l & 3);

    float acc[2][2][4] = {};   // [m-tile][n-tile][frag]

#pragma unroll
    for (int g = 0; g < GROUPS_PER; ++g) {
        // groups issued so far: min(g+2, GROUPS_PER-1); need group g complete
        if (g < GROUPS_PER - 2)      cp_wait<2>();
        else if (g == GROUPS_PER - 2) cp_wait<1>();
        else                          cp_wait<0>();
        __syncthreads();              // data visibility + buffer (g-1)&3 released

        if (g + 3 < GROUPS_PER) stage_w(g + 3);   // refill freed buffer early

        const int bufo = (g & (NRING - 1)) * WBUF;
#pragma unroll
        for (int s4 = 0; s4 < 4; ++s4) {
            const int s = g * 4 + s4;          // global k16-step
            unsigned a0[4], a1[4];
            ldsm4(a0[0], a0[1], a0[2], a0[3], xa0 + s * 32);
            ldsm4(a1[0], a1[1], a1[2], a1[3], xa1 + s * 32);

            const int q00 = ws[bufo + wr0 + s4 * 8];
            const int q01 = ws[bufo + wr0 + s4 * 8 + 4];
            const int q10 = ws[bufo + wr1 + s4 * 8];
            const int q11 = ws[bufo + wr1 + s4 * 8 + 4];

            unsigned b0[2], b1[2];
            b0[0] = dq2(q00, AA[0][g], BB[0][g]);
            b0[1] = dq2(q01, AA[0][g], BB[0][g]);
            b1[0] = dq2(q10, AA[1][g], BB[1][g]);
            b1[1] = dq2(q11, AA[1][g], BB[1][g]);

            mma16816(acc[0][0], a0, b0);
            mma16816(acc[0][1], a0, b1);
            mma16816(acc[1][0], a1, b0);
            mma16816(acc[1][1], a1, b1);
        }
    }

    // ---- epilogue: K-split partials via vector reductions ----
#pragma unroll
    for (int tm = 0; tm < 2; ++tm) {
#pragma unroll
        for (int tn = 0; tn < 2; ++tn) {
            const int n = nblock0 + w * 16 + tn * 8 + (l & 3) * 2;
            const int m = tm * 16 + (l >> 2);
            red2(out + (size_t)m * NDIM + n,       acc[tm][tn][0], acc[tm][tn][1]);
            red2(out + (size_t)(m + 8) * NDIM + n, acc[tm][tn][2], acc[tm][tn][3]);
        }
    }
}

extern "C" void kernel_launch(void* const* d_in, const int* in_sizes, int n_in,
                              void* d_out, int out_size) {
    const float* x      = (const float*)d_in[0];
    const int*   pw     = (const int*)d_in[1];
    const float* scales = (const float*)d_in[2];
    const float* zeros  = (const float*)d_in[3];
    const float* bias   = (const float*)d_in[4];
    float* out = (float*)d_out;

    gptq_init<<<(MM * NDIM) / NTHREADS, NTHREADS>>>(bias, out);

    size_t smem = WS_BYTES + (size_t)MM * XROWH * sizeof(__half);  // 73728 + 33280
    cudaFuncSetAttribute(gptq_main, cudaFuncAttributeMaxDynamicSharedMemorySize, (int)smem);

    dim3 grid(NDIM / NBLK, KSPLIT);
    gptq_main<<<grid, NTHREADS, smem>>>(x, pw, scales, zeros, out);
}